// round 12
// baseline (speedup 1.0000x reference)
#include <cuda_runtime.h>
#include <cstdint>
#include <math_constants.h>

#define BB   32
#define LQ   512
#define LK   2048
#define DD   768
#define D4   (DD/4)     // 192
#define NQC  16
#define QPC  (LQ/NQC)   // 32
#define RPW  32         // rows (keys) per warp
#define WPB  4          // warps per block
#define RPB  (RPW*WPB)  // 128 rows per block
#define NCH  (LK/RPB)   // 16 chunks per batch
#define ATPB 128        // k_attn threads per block
#define PAIRS (RPW/2)   // 16
#define ESPL 16
#define EPB  (DD/ESPL)  // 48

typedef unsigned long long u64;

// packed f32x2 helpers (SASS FFMA2/FMUL2 — only reachable via explicit PTX)
__device__ __forceinline__ u64 pack2(float x, float y) {
    u64 r; asm("mov.b64 %0, {%1, %2};" : "=l"(r) : "f"(x), "f"(y)); return r;
}
__device__ __forceinline__ u64 fma2(u64 a, u64 b, u64 c) {
    u64 d; asm("fma.rn.f32x2 %0, %1, %2, %3;" : "=l"(d) : "l"(a), "l"(b), "l"(c)); return d;
}
__device__ __forceinline__ u64 mul2(u64 a, u64 b) {
    u64 d; asm("mul.rn.f32x2 %0, %1, %2;" : "=l"(d) : "l"(a), "l"(b)); return d;
}
__device__ __forceinline__ float hadd2(u64 v) {
    float x, y; asm("mov.b64 {%0, %1}, %2;" : "=f"(x), "=f"(y) : "l"(v)); return x + y;
}

union F4U { float4 f; u64 u[2]; };

// scratch (device globals — no allocation allowed)
__device__ float g_sp  [BB*NQC*DD];
__device__ float g_ssum[BB*DD];
__device__ float g_qsum[BB*DD];
__device__ float g_wp  [ESPL*BB*DD];
__device__ float g_pm  [BB*NCH];
__device__ float g_pl  [BB*NCH];
__device__ float g_pacc[BB*NCH*DD];
__device__ float g_vin [BB*DD];

// ---------------- K1: partial row-sums of sentence_rep over q ----------------
__global__ void k_ssum_part(const float* __restrict__ sr) {
    int qc = blockIdx.x, b = blockIdx.y, d = threadIdx.x;
    const float* p = sr + ((size_t)b*LQ + (size_t)qc*QPC)*DD + d;
    float a0 = 0.f, a1 = 0.f;
#pragma unroll
    for (int q = 0; q < QPC; q += 2) {
        a0 += p[(size_t)q*DD];
        a1 += p[(size_t)(q+1)*DD];
    }
    g_sp[(b*NQC + qc)*DD + d] = a0 + a1;
}

// ---------------- K1b: reduce partials -> s_sum[b,d] ----------------
__global__ void k_ssum_reduce() {
    int b = blockIdx.x, d = threadIdx.x;
    float a = 0.f;
#pragma unroll
    for (int c = 0; c < NQC; c++) a += g_sp[(b*NQC + c)*DD + d];
    g_ssum[b*DD + d] = a;
}

// ---------------- K2: q_sum[b,e] — 8 interleaved dot products per warp ----------------
__global__ void k_qsum(const float* __restrict__ Wq, const float* __restrict__ bq) {
    int e = blockIdx.x;
    __shared__ float wrow[DD];
    for (int i = threadIdx.x; i < D4; i += 128)
        reinterpret_cast<float4*>(wrow)[i] =
            reinterpret_cast<const float4*>(Wq + (size_t)e*DD)[i];
    __syncthreads();
    int warp = threadIdx.x >> 5, lane = threadIdx.x & 31;
    int b0 = warp * 8;

    float4 w[6];
    const float4* w4 = reinterpret_cast<const float4*>(wrow);
#pragma unroll
    for (int i = 0; i < 6; i++) w[i] = w4[lane + 32*i];

    const float4* s4 = reinterpret_cast<const float4*>(g_ssum);
    float acc[8];
#pragma unroll
    for (int j = 0; j < 8; j++) acc[j] = 0.f;

#pragma unroll
    for (int i = 0; i < 6; i++) {
#pragma unroll
        for (int j = 0; j < 8; j++) {
            float4 s = s4[(size_t)(b0 + j)*D4 + lane + 32*i];
            acc[j] = fmaf(w[i].x, s.x, acc[j]);
            acc[j] = fmaf(w[i].y, s.y, acc[j]);
            acc[j] = fmaf(w[i].z, s.z, acc[j]);
            acc[j] = fmaf(w[i].w, s.w, acc[j]);
        }
    }
#pragma unroll
    for (int o = 16; o; o >>= 1) {
#pragma unroll
        for (int j = 0; j < 8; j++)
            acc[j] += __shfl_xor_sync(0xffffffffu, acc[j], o);
    }
    if (lane == 0) {
        float be = 512.0f * bq[e];
#pragma unroll
        for (int j = 0; j < 8; j++)
            g_qsum[(b0 + j)*DD + e] = acc[j] + be;
    }
}

// ---------------- K3: w partials — R3 shape ----------------
__global__ void k_w(const float* __restrict__ Wk) {
    int d  = blockIdx.x * 128 + threadIdx.x;
    int b0 = blockIdx.y * 2;
    int e0 = blockIdx.z * EPB;
    __shared__ float qs[2*EPB];
    if (threadIdx.x < 2*EPB)
        qs[threadIdx.x] = g_qsum[(b0 + threadIdx.x/EPB)*DD + e0 + (threadIdx.x % EPB)];
    __syncthreads();
    float a0 = 0.f, a1 = 0.f;
#pragma unroll 8
    for (int e = 0; e < EPB; e++) {
        float wk = Wk[(size_t)(e0 + e)*DD + d];
        a0 = fmaf(wk, qs[e],       a0);
        a1 = fmaf(wk, qs[EPB + e], a1);
    }
    int z = blockIdx.z;
    g_wp[(z*BB + b0+0)*DD + d] = a0;
    g_wp[(z*BB + b0+1)*DD + d] = a1;
}

// ---------------- K4 helpers ----------------
__device__ __forceinline__ void load_pair(F4U* v0, F4U* v1,
                                          const float4* rbase, int r) {
    const float4* row0 = rbase + (size_t)r*D4;
    const float4* row1 = row0 + D4;
#pragma unroll
    for (int i = 0; i < 6; i++) v0[i].f = row0[32*i];
#pragma unroll
    for (int i = 0; i < 6; i++) v1[i].f = row1[32*i];
}

__device__ __forceinline__ void process_pair(const F4U* v0, const F4U* v1,
                                             const u64* w,
                                             float& m, float& l, u64* acc) {
    u64 s0p = 0ull, s1p = 0ull;
#pragma unroll
    for (int i = 0; i < 6; i++) {
        s0p = fma2(v0[i].u[0], w[2*i],   s0p);
        s0p = fma2(v0[i].u[1], w[2*i+1], s0p);
        s1p = fma2(v1[i].u[0], w[2*i],   s1p);
        s1p = fma2(v1[i].u[1], w[2*i+1], s1p);
    }
    float s0 = hadd2(s0p);
    float s1 = hadd2(s1p);
#pragma unroll
    for (int o = 16; o; o >>= 1) {
        s0 += __shfl_xor_sync(0xffffffffu, s0, o);
        s1 += __shfl_xor_sync(0xffffffffu, s1, o);
    }

    float mnew = fmaxf(m, fmaxf(s0, s1));
    float p0 = __expf(s0 - mnew);
    float p1 = __expf(s1 - mnew);
    if (mnew != m) {                       // warp-uniform branch
        float scale = __expf(m - mnew);    // 0 on first pair (m=-inf)
        l *= scale;
        u64 sc2 = pack2(scale, scale);
#pragma unroll
        for (int j = 0; j < 12; j++) acc[j] = mul2(acc[j], sc2);
        m = mnew;
    }
    l += p0 + p1;

    u64 p0p = pack2(p0, p0);
    u64 p1p = pack2(p1, p1);
#pragma unroll
    for (int i = 0; i < 6; i++) {
        acc[2*i]   = fma2(p0p, v0[i].u[0], acc[2*i]);
        acc[2*i+1] = fma2(p0p, v0[i].u[1], acc[2*i+1]);
        acc[2*i]   = fma2(p1p, v1[i].u[0], acc[2*i]);
        acc[2*i+1] = fma2(p1p, v1[i].u[1], acc[2*i+1]);
    }
}

// ---------------- K4: warp-autonomous, register-double-buffered pipeline ----------
// grid = (NCH, BB) = 512 blocks, 128 threads; regs land naturally (~160), ~3 blocks/SM.
__global__ void __launch_bounds__(ATPB) k_attn(const float* __restrict__ cr) {
    int b = blockIdx.y, ch = blockIdx.x;
    int tid = threadIdx.x, warp = tid >> 5, lane = tid & 31;

    __shared__ float s_ws[DD];
    __shared__ float s_acc[WPB][DD];
    __shared__ float s_m[WPB], s_l[WPB];
    __shared__ float s_f[WPB];

    // ws = sum of e-split partials (L2-resident)
    for (int i = tid; i < DD; i += ATPB) {
        float a = 0.f;
#pragma unroll
        for (int z = 0; z < ESPL; z++) a += g_wp[(z*BB + b)*DD + i];
        s_ws[i] = a;
    }
    __syncthreads();

    // w into packed registers: 12 u64 pairs covering float4 slots lane+32*i
    u64 w[12];
    const float4* ws4 = reinterpret_cast<const float4*>(s_ws);
#pragma unroll
    for (int i = 0; i < 6; i++) {
        F4U t; t.f = ws4[lane + 32*i];
        w[2*i]   = t.u[0];
        w[2*i+1] = t.u[1];
    }

    const float4* rbase = reinterpret_cast<const float4*>(cr) +
                          ((size_t)b*LK + (size_t)ch*RPB + (size_t)warp*RPW)*D4 + lane;

    float m = -CUDART_INF_F, l = 0.f;
    u64 acc[12];
#pragma unroll
    for (int j = 0; j < 12; j++) acc[j] = 0ull;   // (0.0f, 0.0f)

    // software pipeline: two register buffers, loads issued one pair ahead
    F4U a0[6], a1[6], b0[6], b1[6];
    load_pair(a0, a1, rbase, 0);
#pragma unroll
    for (int p = 0; p < PAIRS; p += 2) {
        if (p + 1 < PAIRS) load_pair(b0, b1, rbase, 2*(p+1));
        process_pair(a0, a1, w, m, l, acc);
        if (p + 2 < PAIRS) load_pair(a0, a1, rbase, 2*(p+2));
        if (p + 1 < PAIRS) process_pair(b0, b1, w, m, l, acc);
    }

    // per-warp results to smem (same float4-slot layout -> natural dim order)
    if (lane == 0) { s_m[warp] = m; s_l[warp] = l; }
    float4* sa = reinterpret_cast<float4*>(s_acc[warp]);
#pragma unroll
    for (int i = 0; i < 6; i++) {
        F4U t; t.u[0] = acc[2*i]; t.u[1] = acc[2*i+1];
        sa[lane + 32*i] = t.f;
    }
    __syncthreads();

    // block combine -> chunk partial
    if (tid == 0) {
        float M = -CUDART_INF_F;
#pragma unroll
        for (int ww = 0; ww < WPB; ww++) M = fmaxf(M, s_m[ww]);
        float L = 0.f;
#pragma unroll
        for (int ww = 0; ww < WPB; ww++) {
            float f = __expf(s_m[ww] - M);
            s_f[ww] = f;
            L += s_l[ww] * f;
        }
        int cidx = b*NCH + ch;
        g_pm[cidx] = M; g_pl[cidx] = L;
    }
    __syncthreads();
    for (int i = tid; i < D4; i += ATPB) {
        float4 a = make_float4(0.f,0.f,0.f,0.f);
#pragma unroll
        for (int ww = 0; ww < WPB; ww++) {
            float f = s_f[ww];
            float4 v = reinterpret_cast<const float4*>(s_acc[ww])[i];
            a.x = fmaf(f, v.x, a.x); a.y = fmaf(f, v.y, a.y);
            a.z = fmaf(f, v.z, a.z); a.w = fmaf(f, v.w, a.w);
        }
        reinterpret_cast<float4*>(g_pacc)[(b*NCH + ch)*D4 + i] = a;
    }
}

// ---------------- K5a: combine chunk partials -> v_in[b,d] ----------------
__global__ void k_comb() {
    int b = blockIdx.x, tid = threadIdx.x;   // 192 threads
    __shared__ float f[NCH];
    __shared__ float invL;
    if (tid == 0) {
        float M = -CUDART_INF_F;
        for (int c = 0; c < NCH; c++) M = fmaxf(M, g_pm[b*NCH + c]);
        float L = 0.f;
        for (int c = 0; c < NCH; c++) {
            float fc = __expf(g_pm[b*NCH + c] - M);
            f[c] = fc;
            L += g_pl[b*NCH + c] * fc;
        }
        invL = 1.0f / L;
    }
    __syncthreads();
    float4 v = make_float4(0.f, 0.f, 0.f, 0.f);
#pragma unroll
    for (int c = 0; c < NCH; c++) {
        float fc = f[c];
        float4 a = reinterpret_cast<const float4*>(g_pacc)[(b*NCH + c)*D4 + tid];
        v.x = fmaf(a.x, fc, v.x); v.y = fmaf(a.y, fc, v.y);
        v.z = fmaf(a.z, fc, v.z); v.w = fmaf(a.w, fc, v.w);
    }
    v.x *= invL; v.y *= invL; v.z *= invL; v.w *= invL;
    reinterpret_cast<float4*>(g_vin)[b*D4 + tid] = v;
}

// ---------------- K5b: out[b,e] = v_in[b,:]·Wv[e,:] + bv[e] ----------------
__global__ void k_out(const float* __restrict__ Wv, const float* __restrict__ bv,
                      float* __restrict__ out) {
    int e = blockIdx.x;
    __shared__ float wrow[DD];
    for (int i = threadIdx.x; i < D4; i += 128)
        reinterpret_cast<float4*>(wrow)[i] =
            reinterpret_cast<const float4*>(Wv + (size_t)e*DD)[i];
    __syncthreads();
    int warp = threadIdx.x >> 5, lane = threadIdx.x & 31;
    float bve = bv[e];
    const float4* w4 = reinterpret_cast<const float4*>(wrow);
    for (int b = warp; b < BB; b += 4) {
        const float4* v4 = reinterpret_cast<const float4*>(g_vin + b*DD);
        float acc = 0.f;
#pragma unroll
        for (int i = 0; i < D4/32; i++) {
            float4 w = w4[lane + 32*i], v = v4[lane + 32*i];
            acc = fmaf(w.x, v.x, acc); acc = fmaf(w.y, v.y, acc);
            acc = fmaf(w.z, v.z, acc); acc = fmaf(w.w, v.w, acc);
        }
#pragma unroll
        for (int o = 16; o; o >>= 1) acc += __shfl_xor_sync(0xffffffffu, acc, o);
        if (lane == 0) out[b*DD + e] = acc + bve;
    }
}

extern "C" void kernel_launch(void* const* d_in, const int* in_sizes, int n_in,
                              void* d_out, int out_size) {
    const float* sr = (const float*)d_in[0];   // sentence_rep [32,512,768]
    const float* cr = (const float*)d_in[1];   // comment_rep  [32,2048,768]
    const float* Wq = (const float*)d_in[2];
    const float* bq = (const float*)d_in[3];
    const float* Wk = (const float*)d_in[4];
    // d_in[5] = bk — exactly cancels in softmax, unused
    const float* Wv = (const float*)d_in[6];
    const float* bv = (const float*)d_in[7];
    float* out = (float*)d_out;

    k_ssum_part<<<dim3(NQC, BB), DD>>>(sr);
    k_ssum_reduce<<<BB, DD>>>();
    k_qsum<<<DD, 128>>>(Wq, bq);
    k_w<<<dim3(DD/128, BB/2, ESPL), 128>>>(Wk);
    k_attn<<<dim3(NCH, BB), ATPB>>>(cr);
    k_comb<<<BB, D4>>>();
    k_out<<<DD, 128>>>(Wv, bv, out);
}

// round 13
// speedup vs baseline: 1.1761x; 1.1761x over previous
#include <cuda_runtime.h>
#include <cstdint>
#include <math_constants.h>

#define BB   32
#define LQ   512
#define LK   2048
#define DD   768
#define D4   (DD/4)     // 192
#define NQC  16
#define QPC  (LQ/NQC)   // 32
#define RPW  32         // rows (keys) per warp
#define WPB  8          // warps per block
#define RPB  (RPW*WPB)  // 256 rows per block
#define NCH  (LK/RPB)   // 8 chunks per batch
#define TPB  256
#define PAIRS (RPW/2)   // 16
#define ESPL 16
#define EPB  (DD/ESPL)  // 48

// k_attn dynamic smem: per-warp 2 buffers x 2 rows x DD floats, + ws + m/l/f
#define SMEM_BUF_FLOATS (WPB*2*2*DD)                    // 24576
#define SMEM_TOT_FLOATS (SMEM_BUF_FLOATS + DD + 3*WPB)  // +768+24
#define SMEM_TOT_BYTES  (SMEM_TOT_FLOATS*4)

typedef unsigned long long u64;

// packed f32x2 helpers (SASS FFMA2/FMUL2 — only reachable via explicit PTX)
__device__ __forceinline__ u64 pack2(float x, float y) {
    u64 r; asm("mov.b64 %0, {%1, %2};" : "=l"(r) : "f"(x), "f"(y)); return r;
}
__device__ __forceinline__ u64 fma2(u64 a, u64 b, u64 c) {
    u64 d; asm("fma.rn.f32x2 %0, %1, %2, %3;" : "=l"(d) : "l"(a), "l"(b), "l"(c)); return d;
}
__device__ __forceinline__ u64 mul2(u64 a, u64 b) {
    u64 d; asm("mul.rn.f32x2 %0, %1, %2;" : "=l"(d) : "l"(a), "l"(b)); return d;
}
__device__ __forceinline__ float hadd2(u64 v) {
    float x, y; asm("mov.b64 {%0, %1}, %2;" : "=f"(x), "=f"(y) : "l"(v)); return x + y;
}

union F4U { float4 f; u64 u[2]; };

// scratch (device globals — no allocation allowed)
__device__ float g_sp  [BB*NQC*DD];
__device__ float g_ssum[BB*DD];
__device__ float g_qsum[BB*DD];
__device__ float g_wp  [ESPL*BB*DD];
__device__ float g_pm  [BB*NCH];
__device__ float g_pl  [BB*NCH];
__device__ float g_pacc[BB*NCH*DD];
__device__ float g_vin [BB*DD];

// ---------------- K1: partial row-sums of sentence_rep over q ----------------
__global__ void k_ssum_part(const float* __restrict__ sr) {
    int qc = blockIdx.x, b = blockIdx.y, d = threadIdx.x;
    const float* p = sr + ((size_t)b*LQ + (size_t)qc*QPC)*DD + d;
    float a0 = 0.f, a1 = 0.f;
#pragma unroll
    for (int q = 0; q < QPC; q += 2) {
        a0 += p[(size_t)q*DD];
        a1 += p[(size_t)(q+1)*DD];
    }
    g_sp[(b*NQC + qc)*DD + d] = a0 + a1;
}

// ---------------- K1b: reduce partials -> s_sum[b,d] ----------------
__global__ void k_ssum_reduce() {
    int b = blockIdx.x, d = threadIdx.x;
    float a = 0.f;
#pragma unroll
    for (int c = 0; c < NQC; c++) a += g_sp[(b*NQC + c)*DD + d];
    g_ssum[b*DD + d] = a;
}

// ---------------- K2: q_sum[b,e] — 8 interleaved dot products per warp ----------------
__global__ void k_qsum(const float* __restrict__ Wq, const float* __restrict__ bq) {
    int e = blockIdx.x;
    __shared__ float wrow[DD];
    for (int i = threadIdx.x; i < D4; i += 128)
        reinterpret_cast<float4*>(wrow)[i] =
            reinterpret_cast<const float4*>(Wq + (size_t)e*DD)[i];
    __syncthreads();
    int warp = threadIdx.x >> 5, lane = threadIdx.x & 31;
    int b0 = warp * 8;

    float4 w[6];
    const float4* w4 = reinterpret_cast<const float4*>(wrow);
#pragma unroll
    for (int i = 0; i < 6; i++) w[i] = w4[lane + 32*i];

    const float4* s4 = reinterpret_cast<const float4*>(g_ssum);
    float acc[8];
#pragma unroll
    for (int j = 0; j < 8; j++) acc[j] = 0.f;

#pragma unroll
    for (int i = 0; i < 6; i++) {
#pragma unroll
        for (int j = 0; j < 8; j++) {
            float4 s = s4[(size_t)(b0 + j)*D4 + lane + 32*i];
            acc[j] = fmaf(w[i].x, s.x, acc[j]);
            acc[j] = fmaf(w[i].y, s.y, acc[j]);
            acc[j] = fmaf(w[i].z, s.z, acc[j]);
            acc[j] = fmaf(w[i].w, s.w, acc[j]);
        }
    }
#pragma unroll
    for (int o = 16; o; o >>= 1) {
#pragma unroll
        for (int j = 0; j < 8; j++)
            acc[j] += __shfl_xor_sync(0xffffffffu, acc[j], o);
    }
    if (lane == 0) {
        float be = 512.0f * bq[e];
#pragma unroll
        for (int j = 0; j < 8; j++)
            g_qsum[(b0 + j)*DD + e] = acc[j] + be;
    }
}

// ---------------- K3: w partials — R3 shape ----------------
__global__ void k_w(const float* __restrict__ Wk) {
    int d  = blockIdx.x * 128 + threadIdx.x;
    int b0 = blockIdx.y * 2;
    int e0 = blockIdx.z * EPB;
    __shared__ float qs[2*EPB];
    if (threadIdx.x < 2*EPB)
        qs[threadIdx.x] = g_qsum[(b0 + threadIdx.x/EPB)*DD + e0 + (threadIdx.x % EPB)];
    __syncthreads();
    float a0 = 0.f, a1 = 0.f;
#pragma unroll 8
    for (int e = 0; e < EPB; e++) {
        float wk = Wk[(size_t)(e0 + e)*DD + d];
        a0 = fmaf(wk, qs[e],       a0);
        a1 = fmaf(wk, qs[EPB + e], a1);
    }
    int z = blockIdx.z;
    g_wp[(z*BB + b0+0)*DD + d] = a0;
    g_wp[(z*BB + b0+1)*DD + d] = a1;
}

// ---------------- K4: warp-autonomous, per-warp cp.async double-buffer ----------
// grid = (NCH, BB) = 256 blocks, 256 threads, ~99KB dyn smem -> 2 blocks/SM.
__global__ void __launch_bounds__(TPB) k_attn(const float* __restrict__ cr) {
    int b = blockIdx.y, ch = blockIdx.x;
    int tid = threadIdx.x, warp = tid >> 5, lane = tid & 31;

    extern __shared__ float sm[];
    float* wbuf = sm + warp * (2*2*DD);          // this warp's 2 pair-buffers
    float* s_ws = sm + SMEM_BUF_FLOATS;          // DD
    float* s_m  = s_ws + DD;                     // WPB
    float* s_l  = s_m + WPB;
    float* s_f  = s_l + WPB;

    // ws = sum of e-split partials (L2-resident)
    for (int i = tid; i < DD; i += TPB) {
        float a = 0.f;
#pragma unroll
        for (int z = 0; z < ESPL; z++) a += g_wp[(z*BB + b)*DD + i];
        s_ws[i] = a;
    }
    __syncthreads();

    // w into packed registers
    u64 w[12];
    const float4* ws4 = reinterpret_cast<const float4*>(s_ws);
#pragma unroll
    for (int i = 0; i < 6; i++) {
        F4U t; t.f = ws4[lane + 32*i];
        w[2*i]   = t.u[0];
        w[2*i+1] = t.u[1];
    }

    // gmem base for this warp's 32 rows; lane covers float4 slots lane+32*i
    const float4* gbase = reinterpret_cast<const float4*>(cr) +
                          ((size_t)b*LK + (size_t)ch*RPB + (size_t)warp*RPW)*D4 + lane;
    uint32_t sbase = (uint32_t)__cvta_generic_to_shared(wbuf) + lane*16u;

    // issue cp.async for pair p into buffer q (12 x 16B per lane)
#define ISSUE_PAIR(p, q) do {                                                   \
        const float4* g0 = gbase + (size_t)(2*(p))*D4;                          \
        uint32_t s0 = sbase + (uint32_t)(q)*(2*DD*4);                           \
        _Pragma("unroll")                                                       \
        for (int i = 0; i < 6; i++) {                                           \
            asm volatile("cp.async.cg.shared.global [%0], [%1], 16;\n"          \
                :: "r"(s0 + i*512u), "l"(g0 + 32*i));                           \
            asm volatile("cp.async.cg.shared.global [%0], [%1], 16;\n"          \
                :: "r"(s0 + (uint32_t)(DD*4) + i*512u), "l"(g0 + D4 + 32*i));   \
        }                                                                       \
        asm volatile("cp.async.commit_group;\n");                               \
    } while (0)

    float m = -CUDART_INF_F, l = 0.f;
    u64 acc[12];
#pragma unroll
    for (int j = 0; j < 12; j++) acc[j] = 0ull;

    ISSUE_PAIR(0, 0);
    ISSUE_PAIR(1, 1);

#pragma unroll 4
    for (int p = 0; p < PAIRS; p++) {
        if (p + 1 < PAIRS) asm volatile("cp.async.wait_group 1;\n" ::: "memory");
        else               asm volatile("cp.async.wait_group 0;\n" ::: "memory");

        const float4* r0 = reinterpret_cast<const float4*>(wbuf + (p & 1)*(2*DD)) + lane;

        // score phase: read from smem, consume immediately
        u64 s0p = 0ull, s1p = 0ull;
#pragma unroll
        for (int i = 0; i < 6; i++) {
            F4U a0; a0.f = r0[32*i];
            F4U a1; a1.f = r0[D4 + 32*i];
            s0p = fma2(a0.u[0], w[2*i],   s0p);
            s0p = fma2(a0.u[1], w[2*i+1], s0p);
            s1p = fma2(a1.u[0], w[2*i],   s1p);
            s1p = fma2(a1.u[1], w[2*i+1], s1p);
        }
        float s0 = hadd2(s0p);
        float s1 = hadd2(s1p);
#pragma unroll
        for (int o = 16; o; o >>= 1) {
            s0 += __shfl_xor_sync(0xffffffffu, s0, o);
            s1 += __shfl_xor_sync(0xffffffffu, s1, o);
        }

        float mnew = fmaxf(m, fmaxf(s0, s1));
        float p0 = __expf(s0 - mnew);
        float p1 = __expf(s1 - mnew);
        if (mnew != m) {                       // warp-uniform branch
            float scale = __expf(m - mnew);    // 0 on first pair (m=-inf)
            l *= scale;
            u64 sc2 = pack2(scale, scale);
#pragma unroll
            for (int j = 0; j < 12; j++) acc[j] = mul2(acc[j], sc2);
            m = mnew;
        }
        l += p0 + p1;

        // acc phase: re-read the same smem slots (this lane wrote them)
        u64 p0p = pack2(p0, p0);
        u64 p1p = pack2(p1, p1);
#pragma unroll
        for (int i = 0; i < 6; i++) {
            F4U a0; a0.f = r0[32*i];
            F4U a1; a1.f = r0[D4 + 32*i];
            acc[2*i]   = fma2(p0p, a0.u[0], acc[2*i]);
            acc[2*i+1] = fma2(p0p, a0.u[1], acc[2*i+1]);
            acc[2*i]   = fma2(p1p, a1.u[0], acc[2*i]);
            acc[2*i+1] = fma2(p1p, a1.u[1], acc[2*i+1]);
        }

        // prefetch pair p+2 into the buffer just freed
        if (p + 2 < PAIRS) ISSUE_PAIR(p + 2, p & 1);
    }

    // per-warp results: reuse this warp's buffer region for acc rows
    if (lane == 0) { s_m[warp] = m; s_l[warp] = l; }
    float4* sa = reinterpret_cast<float4*>(wbuf);
#pragma unroll
    for (int i = 0; i < 6; i++) {
        F4U t; t.u[0] = acc[2*i]; t.u[1] = acc[2*i+1];
        sa[lane + 32*i] = t.f;
    }
    __syncthreads();

    // block combine -> chunk partial
    if (tid == 0) {
        float M = -CUDART_INF_F;
#pragma unroll
        for (int ww = 0; ww < WPB; ww++) M = fmaxf(M, s_m[ww]);
        float L = 0.f;
#pragma unroll
        for (int ww = 0; ww < WPB; ww++) {
            float f = __expf(s_m[ww] - M);
            s_f[ww] = f;
            L += s_l[ww] * f;
        }
        int cidx = b*NCH + ch;
        g_pm[cidx] = M; g_pl[cidx] = L;
    }
    __syncthreads();
    if (tid < D4) {
        float4 a = make_float4(0.f,0.f,0.f,0.f);
#pragma unroll
        for (int ww = 0; ww < WPB; ww++) {
            float f = s_f[ww];
            float4 v = reinterpret_cast<const float4*>(sm + ww*(2*2*DD))[tid];
            a.x = fmaf(f, v.x, a.x); a.y = fmaf(f, v.y, a.y);
            a.z = fmaf(f, v.z, a.z); a.w = fmaf(f, v.w, a.w);
        }
        reinterpret_cast<float4*>(g_pacc)[(b*NCH + ch)*D4 + tid] = a;
    }
}

// ---------------- K5a: combine chunk partials -> v_in[b,d] ----------------
__global__ void k_comb() {
    int b = blockIdx.x, tid = threadIdx.x;   // 192 threads
    __shared__ float f[NCH];
    __shared__ float invL;
    if (tid == 0) {
        float M = -CUDART_INF_F;
        for (int c = 0; c < NCH; c++) M = fmaxf(M, g_pm[b*NCH + c]);
        float L = 0.f;
        for (int c = 0; c < NCH; c++) {
            float fc = __expf(g_pm[b*NCH + c] - M);
            f[c] = fc;
            L += g_pl[b*NCH + c] * fc;
        }
        invL = 1.0f / L;
    }
    __syncthreads();
    float4 v = make_float4(0.f, 0.f, 0.f, 0.f);
#pragma unroll
    for (int c = 0; c < NCH; c++) {
        float fc = f[c];
        float4 a = reinterpret_cast<const float4*>(g_pacc)[(b*NCH + c)*D4 + tid];
        v.x = fmaf(a.x, fc, v.x); v.y = fmaf(a.y, fc, v.y);
        v.z = fmaf(a.z, fc, v.z); v.w = fmaf(a.w, fc, v.w);
    }
    v.x *= invL; v.y *= invL; v.z *= invL; v.w *= invL;
    reinterpret_cast<float4*>(g_vin)[b*D4 + tid] = v;
}

// ---------------- K5b: out[b,e] = v_in[b,:]·Wv[e,:] + bv[e] ----------------
__global__ void k_out(const float* __restrict__ Wv, const float* __restrict__ bv,
                      float* __restrict__ out) {
    int e = blockIdx.x;
    __shared__ float wrow[DD];
    for (int i = threadIdx.x; i < D4; i += 128)
        reinterpret_cast<float4*>(wrow)[i] =
            reinterpret_cast<const float4*>(Wv + (size_t)e*DD)[i];
    __syncthreads();
    int warp = threadIdx.x >> 5, lane = threadIdx.x & 31;
    float bve = bv[e];
    const float4* w4 = reinterpret_cast<const float4*>(wrow);
    for (int b = warp; b < BB; b += 4) {
        const float4* v4 = reinterpret_cast<const float4*>(g_vin + b*DD);
        float acc = 0.f;
#pragma unroll
        for (int i = 0; i < D4/32; i++) {
            float4 w = w4[lane + 32*i], v = v4[lane + 32*i];
            acc = fmaf(w.x, v.x, acc); acc = fmaf(w.y, v.y, acc);
            acc = fmaf(w.z, v.z, acc); acc = fmaf(w.w, v.w, acc);
        }
#pragma unroll
        for (int o = 16; o; o >>= 1) acc += __shfl_xor_sync(0xffffffffu, acc, o);
        if (lane == 0) out[b*DD + e] = acc + bve;
    }
}

extern "C" void kernel_launch(void* const* d_in, const int* in_sizes, int n_in,
                              void* d_out, int out_size) {
    const float* sr = (const float*)d_in[0];   // sentence_rep [32,512,768]
    const float* cr = (const float*)d_in[1];   // comment_rep  [32,2048,768]
    const float* Wq = (const float*)d_in[2];
    const float* bq = (const float*)d_in[3];
    const float* Wk = (const float*)d_in[4];
    // d_in[5] = bk — exactly cancels in softmax, unused
    const float* Wv = (const float*)d_in[6];
    const float* bv = (const float*)d_in[7];
    float* out = (float*)d_out;

    k_ssum_part<<<dim3(NQC, BB), DD>>>(sr);
    k_ssum_reduce<<<BB, DD>>>();
    k_qsum<<<DD, 128>>>(Wq, bq);
    k_w<<<dim3(DD/128, BB/2, ESPL), 128>>>(Wk);

    cudaFuncSetAttribute(k_attn, cudaFuncAttributeMaxDynamicSharedMemorySize,
                         SMEM_TOT_BYTES);
    k_attn<<<dim3(NCH, BB), TPB, SMEM_TOT_BYTES>>>(cr);

    k_comb<<<BB, D4>>>();
    k_out<<<DD, 128>>>(Wv, bv, out);
}

// round 14
// speedup vs baseline: 1.2540x; 1.0663x over previous
#include <cuda_runtime.h>
#include <cstdint>
#include <math_constants.h>

#define BB   32
#define LQ   512
#define LK   2048
#define DD   768
#define D4   (DD/4)     // 192
#define NQC  16
#define QPC  (LQ/NQC)   // 32
#define RPW  32         // rows (keys) per warp
#define WPB  8          // warps per block
#define RPB  (RPW*WPB)  // 256 rows per block
#define NCH  (LK/RPB)   // 8 chunks per batch
#define TPB  256
#define ESPL 16
#define EPB  (DD/ESPL)  // 48

typedef unsigned long long u64;

// packed f32x2 helpers (SASS FFMA2/FMUL2 — only reachable via explicit PTX)
__device__ __forceinline__ u64 pack2(float x, float y) {
    u64 r; asm("mov.b64 %0, {%1, %2};" : "=l"(r) : "f"(x), "f"(y)); return r;
}
__device__ __forceinline__ u64 fma2(u64 a, u64 b, u64 c) {
    u64 d; asm("fma.rn.f32x2 %0, %1, %2, %3;" : "=l"(d) : "l"(a), "l"(b), "l"(c)); return d;
}
__device__ __forceinline__ u64 mul2(u64 a, u64 b) {
    u64 d; asm("mul.rn.f32x2 %0, %1, %2;" : "=l"(d) : "l"(a), "l"(b)); return d;
}
__device__ __forceinline__ float hadd2(u64 v) {
    float x, y; asm("mov.b64 {%0, %1}, %2;" : "=f"(x), "=f"(y) : "l"(v)); return x + y;
}

union F4U { float4 f; u64 u[2]; };

// scratch (device globals — no allocation allowed)
__device__ float g_sp  [BB*NQC*DD];
__device__ float g_ssum[BB*DD];
__device__ float g_qsum[BB*DD];
__device__ float g_wp  [ESPL*BB*DD];
__device__ float g_pm  [BB*NCH];
__device__ float g_pl  [BB*NCH];
__device__ float g_pacc[BB*NCH*DD];
__device__ float g_vin [BB*DD];
__device__ int   g_cnt [BB];    // zero-init; self-resets each use

// ---------------- K1: row-sums of sentence_rep, fused partial+reduce ----------------
// grid (NQC, BB), 192 threads, float4 lanes. Last block per b reduces (fixed order).
__global__ void k_ssum(const float* __restrict__ sr) {
    int qc = blockIdx.x, b = blockIdx.y, t = threadIdx.x;   // t < 192
    const float4* p = reinterpret_cast<const float4*>(sr) +
                      ((size_t)b*LQ + (size_t)qc*QPC)*D4 + t;
    float4 a = make_float4(0.f,0.f,0.f,0.f);
#pragma unroll
    for (int q = 0; q < QPC; q++) {
        float4 v = p[(size_t)q*D4];
        a.x += v.x; a.y += v.y; a.z += v.z; a.w += v.w;
    }
    reinterpret_cast<float4*>(g_sp)[(b*NQC + qc)*D4 + t] = a;

    __threadfence();
    __syncthreads();
    __shared__ int s_last;
    if (t == 0) s_last = (atomicAdd(&g_cnt[b], 1) == NQC-1);
    __syncthreads();
    if (s_last) {
        if (t == 0) g_cnt[b] = 0;   // reset for next graph replay
        float4 r = make_float4(0.f,0.f,0.f,0.f);
#pragma unroll
        for (int c = 0; c < NQC; c++) {
            float4 v = reinterpret_cast<const float4*>(g_sp)[(b*NQC + c)*D4 + t];
            r.x += v.x; r.y += v.y; r.z += v.z; r.w += v.w;
        }
        reinterpret_cast<float4*>(g_ssum)[b*D4 + t] = r;
    }
}

// ---------------- K2: q_sum[b,e] — 8 interleaved dot products per warp ----------------
__global__ void k_qsum(const float* __restrict__ Wq, const float* __restrict__ bq) {
    int e = blockIdx.x;
    __shared__ float wrow[DD];
    for (int i = threadIdx.x; i < D4; i += 128)
        reinterpret_cast<float4*>(wrow)[i] =
            reinterpret_cast<const float4*>(Wq + (size_t)e*DD)[i];
    __syncthreads();
    int warp = threadIdx.x >> 5, lane = threadIdx.x & 31;
    int b0 = warp * 8;

    float4 w[6];
    const float4* w4 = reinterpret_cast<const float4*>(wrow);
#pragma unroll
    for (int i = 0; i < 6; i++) w[i] = w4[lane + 32*i];

    const float4* s4 = reinterpret_cast<const float4*>(g_ssum);
    float acc[8];
#pragma unroll
    for (int j = 0; j < 8; j++) acc[j] = 0.f;

#pragma unroll
    for (int i = 0; i < 6; i++) {
#pragma unroll
        for (int j = 0; j < 8; j++) {
            float4 s = s4[(size_t)(b0 + j)*D4 + lane + 32*i];
            acc[j] = fmaf(w[i].x, s.x, acc[j]);
            acc[j] = fmaf(w[i].y, s.y, acc[j]);
            acc[j] = fmaf(w[i].z, s.z, acc[j]);
            acc[j] = fmaf(w[i].w, s.w, acc[j]);
        }
    }
#pragma unroll
    for (int o = 16; o; o >>= 1) {
#pragma unroll
        for (int j = 0; j < 8; j++)
            acc[j] += __shfl_xor_sync(0xffffffffu, acc[j], o);
    }
    if (lane == 0) {
        float be = 512.0f * bq[e];
#pragma unroll
        for (int j = 0; j < 8; j++)
            g_qsum[(b0 + j)*DD + e] = acc[j] + be;
    }
}

// ---------------- K3: w partials — R3 shape, FULL unroll for MLP ----------------
// grid = (DD/128, BB/2, ESPL) = 1536 blocks, 128 threads
__global__ void k_w(const float* __restrict__ Wk) {
    int d  = blockIdx.x * 128 + threadIdx.x;
    int b0 = blockIdx.y * 2;
    int e0 = blockIdx.z * EPB;
    __shared__ float qs[2*EPB];
    if (threadIdx.x < 2*EPB)
        qs[threadIdx.x] = g_qsum[(b0 + threadIdx.x/EPB)*DD + e0 + (threadIdx.x % EPB)];
    __syncthreads();
    float a0 = 0.f, a1 = 0.f;
#pragma unroll
    for (int e = 0; e < EPB; e++) {
        float wk = Wk[(size_t)(e0 + e)*DD + d];
        a0 = fmaf(wk, qs[e],       a0);
        a1 = fmaf(wk, qs[EPB + e], a1);
    }
    int z = blockIdx.z;
    g_wp[(z*BB + b0+0)*DD + d] = a0;
    g_wp[(z*BB + b0+1)*DD + d] = a1;
}

// ---------------- K4: warp-autonomous, 2 rows/iter, packed f32x2 (R10, 74.2us best) ----
// grid = (NCH, BB) = 256 blocks, 256 threads.
__global__ void __launch_bounds__(TPB) k_attn(const float* __restrict__ cr) {
    int b = blockIdx.y, ch = blockIdx.x;
    int tid = threadIdx.x, warp = tid >> 5, lane = tid & 31;

    __shared__ float s_ws[DD];
    __shared__ float s_acc[WPB][DD];
    __shared__ float s_m[WPB], s_l[WPB];
    __shared__ float s_f[WPB];

    // ws = sum of e-split partials (L2-resident)
    for (int i = tid; i < DD; i += TPB) {
        float a = 0.f;
#pragma unroll
        for (int z = 0; z < ESPL; z++) a += g_wp[(z*BB + b)*DD + i];
        s_ws[i] = a;
    }
    __syncthreads();

    // w into packed registers: 12 u64 pairs covering float4 slots lane+32*i
    u64 w[12];
    const float4* ws4 = reinterpret_cast<const float4*>(s_ws);
#pragma unroll
    for (int i = 0; i < 6; i++) {
        F4U t; t.f = ws4[lane + 32*i];
        w[2*i]   = t.u[0];
        w[2*i+1] = t.u[1];
    }

    const float4* rbase = reinterpret_cast<const float4*>(cr) +
                          ((size_t)b*LK + (size_t)ch*RPB + (size_t)warp*RPW)*D4 + lane;

    float m = -CUDART_INF_F, l = 0.f;
    u64 acc[12];
#pragma unroll
    for (int j = 0; j < 12; j++) acc[j] = 0ull;   // (0.0f, 0.0f)

    for (int r = 0; r < RPW; r += 2) {
        F4U v0[6], v1[6];
        const float4* row0 = rbase + (size_t)r*D4;
        const float4* row1 = row0 + D4;
#pragma unroll
        for (int i = 0; i < 6; i++) v0[i].f = row0[32*i];
#pragma unroll
        for (int i = 0; i < 6; i++) v1[i].f = row1[32*i];

        // packed dot products (24 FFMA2 instead of 48 FFMA)
        u64 s0p = 0ull, s1p = 0ull;
#pragma unroll
        for (int i = 0; i < 6; i++) {
            s0p = fma2(v0[i].u[0], w[2*i],   s0p);
            s0p = fma2(v0[i].u[1], w[2*i+1], s0p);
            s1p = fma2(v1[i].u[0], w[2*i],   s1p);
            s1p = fma2(v1[i].u[1], w[2*i+1], s1p);
        }
        float s0 = hadd2(s0p);
        float s1 = hadd2(s1p);
#pragma unroll
        for (int o = 16; o; o >>= 1) {
            s0 += __shfl_xor_sync(0xffffffffu, s0, o);
            s1 += __shfl_xor_sync(0xffffffffu, s1, o);
        }

        float mnew = fmaxf(m, fmaxf(s0, s1));
        float p0 = __expf(s0 - mnew);
        float p1 = __expf(s1 - mnew);
        if (mnew != m) {                       // warp-uniform branch
            float scale = __expf(m - mnew);    // 0 on first pair (m=-inf)
            l *= scale;
            u64 sc2 = pack2(scale, scale);
#pragma unroll
            for (int j = 0; j < 12; j++) acc[j] = mul2(acc[j], sc2);
            m = mnew;
        }
        l += p0 + p1;

        u64 p0p = pack2(p0, p0);
        u64 p1p = pack2(p1, p1);
#pragma unroll
        for (int i = 0; i < 6; i++) {
            acc[2*i]   = fma2(p0p, v0[i].u[0], acc[2*i]);
            acc[2*i+1] = fma2(p0p, v0[i].u[1], acc[2*i+1]);
            acc[2*i]   = fma2(p1p, v1[i].u[0], acc[2*i]);
            acc[2*i+1] = fma2(p1p, v1[i].u[1], acc[2*i+1]);
        }
    }

    // per-warp results to smem (same float4-slot layout -> natural dim order)
    if (lane == 0) { s_m[warp] = m; s_l[warp] = l; }
    float4* sa = reinterpret_cast<float4*>(s_acc[warp]);
#pragma unroll
    for (int i = 0; i < 6; i++) {
        F4U t; t.u[0] = acc[2*i]; t.u[1] = acc[2*i+1];
        sa[lane + 32*i] = t.f;
    }
    __syncthreads();

    // block combine -> chunk partial
    if (tid == 0) {
        float M = -CUDART_INF_F;
#pragma unroll
        for (int ww = 0; ww < WPB; ww++) M = fmaxf(M, s_m[ww]);
        float L = 0.f;
#pragma unroll
        for (int ww = 0; ww < WPB; ww++) {
            float f = __expf(s_m[ww] - M);
            s_f[ww] = f;
            L += s_l[ww] * f;
        }
        int cidx = b*NCH + ch;
        g_pm[cidx] = M; g_pl[cidx] = L;
    }
    __syncthreads();
    if (tid < D4) {
        float4 a = make_float4(0.f,0.f,0.f,0.f);
#pragma unroll
        for (int ww = 0; ww < WPB; ww++) {
            float f = s_f[ww];
            float4 v = reinterpret_cast<const float4*>(s_acc[ww])[tid];
            a.x = fmaf(f, v.x, a.x); a.y = fmaf(f, v.y, a.y);
            a.z = fmaf(f, v.z, a.z); a.w = fmaf(f, v.w, a.w);
        }
        reinterpret_cast<float4*>(g_pacc)[(b*NCH + ch)*D4 + tid] = a;
    }
}

// ---------------- K5a: combine chunk partials -> v_in[b,d] ----------------
__global__ void k_comb() {
    int b = blockIdx.x, tid = threadIdx.x;   // 192 threads
    __shared__ float f[NCH];
    __shared__ float invL;
    if (tid == 0) {
        float M = -CUDART_INF_F;
        for (int c = 0; c < NCH; c++) M = fmaxf(M, g_pm[b*NCH + c]);
        float L = 0.f;
        for (int c = 0; c < NCH; c++) {
            float fc = __expf(g_pm[b*NCH + c] - M);
            f[c] = fc;
            L += g_pl[b*NCH + c] * fc;
        }
        invL = 1.0f / L;
    }
    __syncthreads();
    float4 v = make_float4(0.f, 0.f, 0.f, 0.f);
#pragma unroll
    for (int c = 0; c < NCH; c++) {
        float fc = f[c];
        float4 a = reinterpret_cast<const float4*>(g_pacc)[(b*NCH + c)*D4 + tid];
        v.x = fmaf(a.x, fc, v.x); v.y = fmaf(a.y, fc, v.y);
        v.z = fmaf(a.z, fc, v.z); v.w = fmaf(a.w, fc, v.w);
    }
    v.x *= invL; v.y *= invL; v.z *= invL; v.w *= invL;
    reinterpret_cast<float4*>(g_vin)[b*D4 + tid] = v;
}

// ---------------- K5b: out[b,e] = v_in[b,:]·Wv[e,:] + bv[e] ----------------
__global__ void k_out(const float* __restrict__ Wv, const float* __restrict__ bv,
                      float* __restrict__ out) {
    int e = blockIdx.x;
    __shared__ float wrow[DD];
    for (int i = threadIdx.x; i < D4; i += 128)
        reinterpret_cast<float4*>(wrow)[i] =
            reinterpret_cast<const float4*>(Wv + (size_t)e*DD)[i];
    __syncthreads();
    int warp = threadIdx.x >> 5, lane = threadIdx.x & 31;
    float bve = bv[e];
    const float4* w4 = reinterpret_cast<const float4*>(wrow);
    for (int b = warp; b < BB; b += 4) {
        const float4* v4 = reinterpret_cast<const float4*>(g_vin + b*DD);
        float acc = 0.f;
#pragma unroll
        for (int i = 0; i < D4/32; i++) {
            float4 w = w4[lane + 32*i], v = v4[lane + 32*i];
            acc = fmaf(w.x, v.x, acc); acc = fmaf(w.y, v.y, acc);
            acc = fmaf(w.z, v.z, acc); acc = fmaf(w.w, v.w, acc);
        }
#pragma unroll
        for (int o = 16; o; o >>= 1) acc += __shfl_xor_sync(0xffffffffu, acc, o);
        if (lane == 0) out[b*DD + e] = acc + bve;
    }
}

extern "C" void kernel_launch(void* const* d_in, const int* in_sizes, int n_in,
                              void* d_out, int out_size) {
    const float* sr = (const float*)d_in[0];   // sentence_rep [32,512,768]
    const float* cr = (const float*)d_in[1];   // comment_rep  [32,2048,768]
    const float* Wq = (const float*)d_in[2];
    const float* bq = (const float*)d_in[3];
    const float* Wk = (const float*)d_in[4];
    // d_in[5] = bk — exactly cancels in softmax, unused
    const float* Wv = (const float*)d_in[6];
    const float* bv = (const float*)d_in[7];
    float* out = (float*)d_out;

    k_ssum<<<dim3(NQC, BB), D4>>>(sr);
    k_qsum<<<DD, 128>>>(Wq, bq);
    k_w<<<dim3(DD/128, BB/2, ESPL), 128>>>(Wk);
    k_attn<<<dim3(NCH, BB), TPB>>>(cr);
    k_comb<<<BB, D4>>>();
    k_out<<<DD, 128>>>(Wv, bv, out);
}